// round 14
// baseline (speedup 1.0000x reference)
#include <cuda_runtime.h>
#include <cuda_bf16.h>
#include <cstdint>

// Problem constants (fixed by setup_inputs)
#define BB 2
#define LL 2048
#define SSS 2048
#define HH 8
#define EE 64

#define BT 64        // L and S tile
#define NTHREADS 128 // 4 warps; warp w owns rows 16w..16w+15

#define PADK 68      // K smem row stride (floats); 272B = 17x16B (odd -> conflict-free)
#define PADV 68      // V smem row stride (e-rows)
#define PADP 68      // P smem row stride

#define MASK_SCALE 10000.0f
#define NEG_BIG (-1e30f)
#define SCALE 0.125f  // 1/sqrt(64), exact power of two

// Precomputed additive mask: madd[h,l,s] = (hard==0) ? NEG_BIG
//                                        : SCALE * 10000 * min(sig-thr, 0)
__device__ float g_madd[HH * LL * SSS];
// K: tf32-rounded, [b][h][s][permK(e)]  (permK(e) = ((e>>2)&1)*32 + (e&3)*8 + (e>>3))
__device__ float g_kt[BB * HH * SSS * EE];
// V: tf32-rounded, tile-blocked transpose: [b][h][st][e][permS(s&63)]
__device__ float g_vt[BB * HH * SSS * EE];

// ---------------------------------------------------------------------------
// helpers
// ---------------------------------------------------------------------------
__device__ __forceinline__ float tf32r(float x) {
    float y;
    asm("cvt.rna.tf32.f32 %0, %1;" : "=f"(y) : "f"(x));
    return y;
}

__device__ __forceinline__ void mma_tf32(float c[4], const uint32_t a[4],
                                         uint32_t b0, uint32_t b1) {
    asm volatile(
        "mma.sync.aligned.m16n8k8.row.col.f32.tf32.tf32.f32 "
        "{%0,%1,%2,%3}, {%4,%5,%6,%7}, {%8,%9}, {%0,%1,%2,%3};"
        : "+f"(c[0]), "+f"(c[1]), "+f"(c[2]), "+f"(c[3])
        : "r"(a[0]), "r"(a[1]), "r"(a[2]), "r"(a[3]),
          "r"(b0), "r"(b1));
}

__device__ __forceinline__ uint32_t smem_u32(const void* p) {
    return (uint32_t)__cvta_generic_to_shared(p);
}

__device__ __forceinline__ void cp_async16(uint32_t dst, const void* src) {
    asm volatile("cp.async.cg.shared.global [%0], [%1], 16;" :: "r"(dst), "l"(src));
}

#define CP_COMMIT() asm volatile("cp.async.commit_group;")
#define CP_WAIT1()  asm volatile("cp.async.wait_group 1;")

// ---------------------------------------------------------------------------
// Kernel 0: round K/V to tf32 once; K -> [b][h][s][permK(e)],
//           V -> [b][h][st][e][permS(sl)]
// ---------------------------------------------------------------------------
__global__ __launch_bounds__(256)
void preround_kv_kernel(const float* __restrict__ kk,
                        const float* __restrict__ vv_)
{
    const int i = (blockIdx.x * 256 + threadIdx.x) * 4;  // linear (b,s,h,e)
    const int e0 = i & (EE - 1);
    const int t  = i >> 6;           // b*S*H + s*H + h
    const int h  = t & (HH - 1);
    const int t2 = t >> 3;           // b*S + s
    const int s  = t2 & (SSS - 1);
    const int b  = t2 >> 11;

    const float4 k4 = *(const float4*)&kk[i];
    const float4 v4 = *(const float4*)&vv_[i];

    // K destination: row (b,h,s), permuted e.  e0 is 4-aligned:
    // permK(e0+j) = ((e0>>2)&1)*32 + (e0>>3) + j*8
    {
        float* kd = g_kt + ((b * HH + h) * SSS + s) * EE
                  + ((e0 >> 2) & 1) * 32 + (e0 >> 3);
        kd[0]  = tf32r(k4.x);
        kd[8]  = tf32r(k4.y);
        kd[16] = tf32r(k4.z);
        kd[24] = tf32r(k4.w);
    }
    // V destination: tile-blocked transpose, e-major rows, permuted s column.
    {
        const int st = s >> 6;
        const int sl = s & 63;
        const int ps = ((sl >> 2) & 1) * 32 + (sl & 3) * 8 + (sl >> 3);
        float* vd = g_vt + (((b * HH + h) * 32 + st) * EE + e0) * 64 + ps;
        vd[0]   = tf32r(v4.x);
        vd[64]  = tf32r(v4.y);
        vd[128] = tf32r(v4.z);
        vd[192] = tf32r(v4.w);
    }
}

// ---------------------------------------------------------------------------
// Kernel 1: precompute the DAG + hard-mask additive term (memory/MUFU-bound)
// ---------------------------------------------------------------------------
__global__ __launch_bounds__(256)
void precompute_madd_kernel(const float* __restrict__ phi,
                            const float* __restrict__ uu_,
                            const int*   __restrict__ hard,
                            const float* __restrict__ log_tau,
                            const float* __restrict__ threshold,
                            const int*   __restrict__ causal_flag)
{
    const int row = blockIdx.y;          // h*LL + l
    const int l   = row & (LL - 1);
    const int s   = (blockIdx.x * 256 + threadIdx.x) * 4;
    if (causal_flag[0] && s > l) return;   // upper triangle never read (causal)

    float tau = __expf(log_tau[0]);
    tau = fminf(fmaxf(tau, 0.1f), 5.0f);
    const float inv_tau = 1.0f / tau;
    float thr = threshold[0];
    thr = fminf(fmaxf(thr, 0.01f), 0.99f);

    const int idx = row * SSS + s;
    const float4 ph = *(const float4*)&phi[idx];
    const float4 uv = *(const float4*)&uu_[idx];
    const int4   hm = *(const int4*)&hard[l * SSS + s];

    float4 o;
    {
        float g = __logf(__fdividef(uv.x + 1e-8f, 1.0f - uv.x + 1e-8f));
        float sg = __fdividef(1.0f, 1.0f + __expf(-(g + ph.x) * inv_tau));
        o.x = hm.x == 0 ? NEG_BIG : SCALE * MASK_SCALE * fminf(sg - thr, 0.0f);
    }
    {
        float g = __logf(__fdividef(uv.y + 1e-8f, 1.0f - uv.y + 1e-8f));
        float sg = __fdividef(1.0f, 1.0f + __expf(-(g + ph.y) * inv_tau));
        o.y = hm.y == 0 ? NEG_BIG : SCALE * MASK_SCALE * fminf(sg - thr, 0.0f);
    }
    {
        float g = __logf(__fdividef(uv.z + 1e-8f, 1.0f - uv.z + 1e-8f));
        float sg = __fdividef(1.0f, 1.0f + __expf(-(g + ph.z) * inv_tau));
        o.z = hm.z == 0 ? NEG_BIG : SCALE * MASK_SCALE * fminf(sg - thr, 0.0f);
    }
    {
        float g = __logf(__fdividef(uv.w + 1e-8f, 1.0f - uv.w + 1e-8f));
        float sg = __fdividef(1.0f, 1.0f + __expf(-(g + ph.w) * inv_tau));
        o.w = hm.w == 0 ? NEG_BIG : SCALE * MASK_SCALE * fminf(sg - thr, 0.0f);
    }
    *(float4*)&g_madd[idx] = o;
}

// ---------------------------------------------------------------------------
// Kernel 2: flash attention on tensor cores (tf32 mma.sync m16n8k8).
// R12 pipeline (K AND V double-buffered, one commit group per tile, single
// wait point), with ALL fragment traffic vectorized to LDS.128 via permuted
// smem layouts (K e-perm, V transposed s-perm, P k-perm).
//
// perm(x) for x = 8*c + d + 4*b (d in 0..3, b in 0..1): offset = b*32 + d*8 + c
// -> a thread's 8 per-k-group fragment words are contiguous (two LDS.128).
// Bank check (quarter-warp, stride 17 x 16B rows): addr16 mod 8 = gid + 2*tig,
// all distinct -> conflict-free.
// ---------------------------------------------------------------------------
__global__ __launch_bounds__(NTHREADS)
void phi_softmax_mma_kernel(const float* __restrict__ q,
                            const int*   __restrict__ causal_flag,
                            float*       __restrict__ out)
{
    extern __shared__ float smem[];
    float* Ks = smem;                             // [2][64][PADK]  (s-rows)
    float* Vs = Ks + 2 * BT * PADK;               // [2][64][PADV]  (e-rows!)
    float* Ps = Vs + 2 * BT * PADV;               // [64][PADP]; also Q staging

    const int b  = blockIdx.x;                    // batch fastest -> madd L2 reuse
    const int h  = blockIdx.y;
    const int lt = gridDim.z - 1 - blockIdx.z;    // heavy tiles first
    const int l0 = lt * BT;

    const int tid  = threadIdx.x;
    const int w    = tid >> 5;
    const int lane = tid & 31;
    const int gid  = lane >> 2;
    const int tig  = lane & 3;

    const int r0 = 16 * w + gid;                  // this thread's two rows
    const int r1 = r0 + 8;
    const int lg0 = l0 + r0;
    const int lg1 = l0 + r1;

    const int causal = causal_flag[0];
    const int nst = causal ? (lt + 1) : (SSS / BT);

    const float* kt      = g_kt + (b * HH + h) * (SSS * EE);
    const float* vt_base = g_vt + (b * HH + h) * (SSS * EE);  // + st*4096

    // per-thread cp.async slice: 8 chunks of 16B for K, 8 for V
    const int cr  = tid >> 4;           // base row (advance by 8)
    const int cec = (tid & 15) * 4;     // column (floats)

    // ---- prologue: issue tile 0 loads (one group: K0+V0) ----
    #pragma unroll
    for (int c = 0; c < 8; c++) {
        const int r = cr + 8 * c;
        cp_async16(smem_u32(&Ks[r * PADK + cec]), &kt[r * EE + cec]);
        cp_async16(smem_u32(&Vs[r * PADV + cec]), &vt_base[r * 64 + cec]);
    }
    CP_COMMIT();

    // ---- stage scaled Q into Ps (linear layout), load Q a-frags ----
    for (int i = tid; i < BT * (EE / 4); i += NTHREADS) {
        int r  = i >> 4;
        int ec = (i & 15) * 4;
        float4 q4 = *(const float4*)&q[((b * LL + l0 + r) * HH + h) * EE + ec];
        Ps[r * PADP + ec + 0] = q4.x * SCALE;
        Ps[r * PADP + ec + 1] = q4.y * SCALE;
        Ps[r * PADP + ec + 2] = q4.z * SCALE;
        Ps[r * PADP + ec + 3] = q4.w * SCALE;
    }
    __syncthreads();

    uint32_t qa[8][4];                            // full K-dim of Q, tf32
    #pragma unroll
    for (int k8 = 0; k8 < 8; k8++) {
        qa[k8][0] = __float_as_uint(tf32r(Ps[r0 * PADP + 8 * k8 + tig]));
        qa[k8][1] = __float_as_uint(tf32r(Ps[r1 * PADP + 8 * k8 + tig]));
        qa[k8][2] = __float_as_uint(tf32r(Ps[r0 * PADP + 8 * k8 + tig + 4]));
        qa[k8][3] = __float_as_uint(tf32r(Ps[r1 * PADP + 8 * k8 + tig + 4]));
    }

    float o[8][4];
    float mrun0 = NEG_BIG, mrun1 = NEG_BIG, lrun0 = 0.0f, lrun1 = 0.0f;
    #pragma unroll
    for (int n = 0; n < 8; n++)
        #pragma unroll
        for (int j = 0; j < 4; j++) o[n][j] = 0.0f;

    const float* maddR0 = g_madd + (h * LL + lg0) * SSS;
    const float* maddR1 = g_madd + (h * LL + lg1) * SSS;

    // P write offsets (permuted k layout): col 8n+2tig -> b*32+d*8+n
    const int pw0 = (tig >> 1) * 32 + (tig & 1) * 16;   // + n; p1 at +8
    // fragment load base (floats): tig*8 (beta=0) / 32+tig*8 (beta=1)
    const int fb0 = tig * 8;
    const int fb1 = 32 + tig * 8;

    for (int st = 0; st < nst; st++) {
        const int s0 = st * BT;
        const float* Kb = Ks + (st & 1) * BT * PADK;
        const float* Vb = Vs + (st & 1) * BT * PADV;

        // Barrier A: all warps done with iter st-1 (GEMM2 reads of Vb/Ps).
        __syncthreads();

        // ---- issue next tile's cp.async (empty group keeps wait uniform) ----
        if (st + 1 < nst) {
            float* Kn = Ks + ((st + 1) & 1) * BT * PADK;
            float* Vn = Vs + ((st + 1) & 1) * BT * PADV;
            const float* ksrc = kt + (s0 + BT) * EE;
            const float* vsrc = vt_base + (st + 1) * (BT * 64);
            #pragma unroll
            for (int c = 0; c < 8; c++) {
                const int r = cr + 8 * c;
                cp_async16(smem_u32(&Kn[r * PADK + cec]), &ksrc[r * EE + cec]);
                cp_async16(smem_u32(&Vn[r * PADV + cec]), &vsrc[r * 64 + cec]);
            }
        }
        CP_COMMIT();
        CP_WAIT1();        // tile st resident; tile st+1 still in flight
        __syncthreads();   // Barrier B: K(st)/V(st) visible to all warps

        // ---- prefetch madd for this tile into registers (overlaps GEMM1) ----
        float2 ma0[8], ma1[8];
        #pragma unroll
        for (int n = 0; n < 8; n++) {
            const int sc = s0 + 8 * n + 2 * tig;
            ma0[n] = *(const float2*)&maddR0[sc];
            ma1[n] = *(const float2*)&maddR1[sc];
        }

        // ---- GEMM1: scores; b-frags via 4x LDS.128 per n-group ----
        float cc[8][4];
        #pragma unroll
        for (int n = 0; n < 8; n++)
            #pragma unroll
            for (int j = 0; j < 4; j++) cc[n][j] = 0.0f;

        #pragma unroll
        for (int n = 0; n < 8; n++) {
            const float* krow = Kb + (8 * n + gid) * PADK;
            const uint4 c0 = *(const uint4*)(krow + fb0);      // b0, k8 0-3
            const uint4 c1 = *(const uint4*)(krow + fb0 + 4);  // b0, k8 4-7
            const uint4 c2 = *(const uint4*)(krow + fb1);      // b1, k8 0-3
            const uint4 c3 = *(const uint4*)(krow + fb1 + 4);  // b1, k8 4-7
            mma_tf32(cc[n], qa[0], c0.x, c2.x);
            mma_tf32(cc[n], qa[1], c0.y, c2.y);
            mma_tf32(cc[n], qa[2], c0.z, c2.z);
            mma_tf32(cc[n], qa[3], c0.w, c2.w);
            mma_tf32(cc[n], qa[4], c1.x, c3.x);
            mma_tf32(cc[n], qa[5], c1.y, c3.y);
            mma_tf32(cc[n], qa[6], c1.z, c3.z);
            mma_tf32(cc[n], qa[7], c1.w, c3.w);
        }

        // ---- additive mask + causal + online softmax ----
        float rmax0 = NEG_BIG, rmax1 = NEG_BIG;
        #pragma unroll
        for (int n = 0; n < 8; n++) {
            const int sc = s0 + 8 * n + 2 * tig;
            float x0 = cc[n][0] + ma0[n].x;
            float x1 = cc[n][1] + ma0[n].y;
            float x2 = cc[n][2] + ma1[n].x;
            float x3 = cc[n][3] + ma1[n].y;
            if (causal) {
                if (sc     > lg0) x0 = NEG_BIG;
                if (sc + 1 > lg0) x1 = NEG_BIG;
                if (sc     > lg1) x2 = NEG_BIG;
                if (sc + 1 > lg1) x3 = NEG_BIG;
            }
            cc[n][0] = x0; cc[n][1] = x1; cc[n][2] = x2; cc[n][3] = x3;
            rmax0 = fmaxf(rmax0, fmaxf(x0, x1));
            rmax1 = fmaxf(rmax1, fmaxf(x2, x3));
        }
        rmax0 = fmaxf(rmax0, __shfl_xor_sync(0xffffffffu, rmax0, 1, 4));
        rmax0 = fmaxf(rmax0, __shfl_xor_sync(0xffffffffu, rmax0, 2, 4));
        rmax1 = fmaxf(rmax1, __shfl_xor_sync(0xffffffffu, rmax1, 1, 4));
        rmax1 = fmaxf(rmax1, __shfl_xor_sync(0xffffffffu, rmax1, 2, 4));

        const float mnew0 = fmaxf(mrun0, rmax0);
        const float mnew1 = fmaxf(mrun1, rmax1);
        const float al0 = __expf(mrun0 - mnew0);
        const float al1 = __expf(mrun1 - mnew1);
        mrun0 = mnew0; mrun1 = mnew1;

        float ls0 = 0.0f, ls1 = 0.0f;
        #pragma unroll
        for (int n = 0; n < 8; n++) {
            // Fully-masked-so-far rows give p=1 garbage; annihilated once the
            // first real entry (open diagonal) makes alpha=exp(-inf)=0.
            float p0 = __expf(cc[n][0] - mnew0);
            float p1 = __expf(cc[n][1] - mnew0);
            float p2 = __expf(cc[n][2] - mnew1);
            float p3 = __expf(cc[n][3] - mnew1);
            ls0 += p0 + p1;
            ls1 += p2 + p3;
            // permuted-k P store: col 8n+2tig -> pw0+n, col +1 -> pw0+n+8
            Ps[r0 * PADP + pw0 + n]     = tf32r(p0);
            Ps[r0 * PADP + pw0 + n + 8] = tf32r(p1);
            Ps[r1 * PADP + pw0 + n]     = tf32r(p2);
            Ps[r1 * PADP + pw0 + n + 8] = tf32r(p3);
        }
        lrun0 = lrun0 * al0 + ls0;
        lrun1 = lrun1 * al1 + ls1;
        #pragma unroll
        for (int n = 0; n < 8; n++) {
            o[n][0] *= al0; o[n][1] *= al0;
            o[n][2] *= al1; o[n][3] *= al1;
        }
        __syncwarp();   // P rows are warp-private; order STS before LDS

        // ---- GEMM2: out += P @ V ----
        // P a-frags: 8x LDS.128 for all 8 k-groups
        const float* p0r = Ps + r0 * PADP;
        const float* p1r = Ps + r1 * PADP;
        const uint4 pA0a = *(const uint4*)(p0r + fb0);
        const uint4 pA0b = *(const uint4*)(p0r + fb0 + 4);
        const uint4 pA1a = *(const uint4*)(p1r + fb0);
        const uint4 pA1b = *(const uint4*)(p1r + fb0 + 4);
        const uint4 pB0a = *(const uint4*)(p0r + fb1);
        const uint4 pB0b = *(const uint4*)(p0r + fb1 + 4);
        const uint4 pB1a = *(const uint4*)(p1r + fb1);
        const uint4 pB1b = *(const uint4*)(p1r + fb1 + 4);
        uint32_t pa[8][4];
        pa[0][0]=pA0a.x; pa[1][0]=pA0a.y; pa[2][0]=pA0a.z; pa[3][0]=pA0a.w;
        pa[4][0]=pA0b.x; pa[5][0]=pA0b.y; pa[6][0]=pA0b.z; pa[7][0]=pA0b.w;
        pa[0][1]=pA1a.x; pa[1][1]=pA1a.y; pa[2][1]=pA1a.z; pa[3][1]=pA1a.w;
        pa[4][1]=pA1b.x; pa[5][1]=pA1b.y; pa[6][1]=pA1b.z; pa[7][1]=pA1b.w;
        pa[0][2]=pB0a.x; pa[1][2]=pB0a.y; pa[2][2]=pB0a.z; pa[3][2]=pB0a.w;
        pa[4][2]=pB0b.x; pa[5][2]=pB0b.y; pa[6][2]=pB0b.z; pa[7][2]=pB0b.w;
        pa[0][3]=pB1a.x; pa[1][3]=pB1a.y; pa[2][3]=pB1a.z; pa[3][3]=pB1a.w;
        pa[4][3]=pB1b.x; pa[5][3]=pB1b.y; pa[6][3]=pB1b.z; pa[7][3]=pB1b.w;

        #pragma unroll
        for (int n = 0; n < 8; n++) {
            const float* vrow = Vb + (8 * n + gid) * PADV;   // e-row 8n+gid
            const uint4 d0 = *(const uint4*)(vrow + fb0);      // b0, kk 0-3
            const uint4 d1 = *(const uint4*)(vrow + fb0 + 4);  // b0, kk 4-7
            const uint4 d2 = *(const uint4*)(vrow + fb1);      // b1, kk 0-3
            const uint4 d3 = *(const uint4*)(vrow + fb1 + 4);  // b1, kk 4-7
            mma_tf32(o[n], pa[0], d0.x, d2.x);
            mma_tf32(o[n], pa[1], d0.y, d2.y);
            mma_tf32(o[n], pa[2], d0.z, d2.z);
            mma_tf32(o[n], pa[3], d0.w, d2.w);
            mma_tf32(o[n], pa[4], d1.x, d3.x);
            mma_tf32(o[n], pa[5], d1.y, d3.y);
            mma_tf32(o[n], pa[6], d1.z, d3.z);
            mma_tf32(o[n], pa[7], d1.w, d3.w);
        }
    }

    // ---- finalize: reduce row sums across quad, normalize, store ----
    lrun0 += __shfl_xor_sync(0xffffffffu, lrun0, 1, 4);
    lrun0 += __shfl_xor_sync(0xffffffffu, lrun0, 2, 4);
    lrun1 += __shfl_xor_sync(0xffffffffu, lrun1, 1, 4);
    lrun1 += __shfl_xor_sync(0xffffffffu, lrun1, 2, 4);
    const float inv0 = 1.0f / lrun0;   // diagonal always open -> lrun > 0
    const float inv1 = 1.0f / lrun1;

    float* out0 = out + ((b * LL + lg0) * HH + h) * EE;
    float* out1 = out + ((b * LL + lg1) * HH + h) * EE;
    #pragma unroll
    for (int n = 0; n < 8; n++) {
        const int ec = 8 * n + 2 * tig;
        *(float2*)&out0[ec] = make_float2(o[n][0] * inv0, o[n][1] * inv0);
        *(float2*)&out1[ec] = make_float2(o[n][2] * inv1, o[n][3] * inv1);
    }
}

extern "C" void kernel_launch(void* const* d_in, const int* in_sizes, int n_in,
                              void* d_out, int out_size)
{
    const float* q        = (const float*)d_in[0];
    const float* k        = (const float*)d_in[1];
    const float* v        = (const float*)d_in[2];
    const int*   causal   = (const int*)d_in[6];
    const int*   hard     = (const int*)d_in[7];
    const float* phi      = (const float*)d_in[8];
    const float* log_tau  = (const float*)d_in[9];
    const float* thr      = (const float*)d_in[10];
    const float* u        = (const float*)d_in[11];
    float* out            = (float*)d_out;

    // Kernel 0: pre-round K/V to tf32 with permuted layouts
    {
        const int n4 = BB * SSS * HH * EE / 4;
        preround_kv_kernel<<<n4 / 256, 256>>>(k, v);
    }

    // Kernel 1: precompute additive mask (batch-independent)
    {
        dim3 grid(SSS / (256 * 4), HH * LL);
        precompute_madd_kernel<<<grid, 256>>>(phi, u, hard, log_tau, thr, causal);
    }

    // Kernel 2: pipelined tensor-core attention, vectorized fragment LDS
    {
        const int smem_bytes =
            (2 * BT * PADK + 2 * BT * PADV + BT * PADP) * sizeof(float);
        cudaFuncSetAttribute(phi_softmax_mma_kernel,
                             cudaFuncAttributeMaxDynamicSharedMemorySize, smem_bytes);
        dim3 grid(BB, HH, LL / BT);
        phi_softmax_mma_kernel<<<grid, NTHREADS, smem_bytes>>>(q, causal, out);
    }
}

// round 16
// speedup vs baseline: 1.3864x; 1.3864x over previous
#include <cuda_runtime.h>
#include <cuda_bf16.h>
#include <cuda_fp16.h>
#include <cstdint>

// Problem constants (fixed by setup_inputs)
#define BB 2
#define LL 2048
#define SSS 2048
#define HH 8
#define EE 64

#define BT 64        // L and S tile
#define NTHREADS 128 // 4 warps; warp w owns rows 16w..16w+15

#define PADK 68      // K smem stride (floats): b-frag banks conflict-free
#define PADV 72      // V smem stride: b-frag banks conflict-free
#define PADP 68      // P smem stride: a-frag banks conflict-free
#define PADM 72      // madd smem stride (halves): 144B rows, conflict-free

#define MASK_SCALE 10000.0f
#define NEG_BIG  (-1e30f)
#define HARD_NEG (-60000.0f)   // fp16-representable sentinel for hard mask
#define LOG2E 1.44269504f
#define SCALE 0.125f            // 1/sqrt(64)
#define SCALE_L (SCALE * LOG2E) // folded into Q; softmax uses exp2

// Precomputed additive mask in LOG2 UNITS, fp16:
//   madd[h,l,s] = hard==0 ? HARD_NEG : LOG2E * SCALE * 10000 * min(sig-thr, 0)
__device__ __half g_madd[HH * LL * SSS];
// K/V pre-rounded to tf32 and transposed to [b][h][s][e]
__device__ float g_kt[BB * HH * SSS * EE];
__device__ float g_vt[BB * HH * SSS * EE];

// ---------------------------------------------------------------------------
// helpers
// ---------------------------------------------------------------------------
__device__ __forceinline__ float tf32r(float x) {
    float y;
    asm("cvt.rna.tf32.f32 %0, %1;" : "=f"(y) : "f"(x));
    return y;
}

__device__ __forceinline__ void mma_tf32(float c[4], const uint32_t a[4],
                                         const uint32_t bfr[2]) {
    asm volatile(
        "mma.sync.aligned.m16n8k8.row.col.f32.tf32.tf32.f32 "
        "{%0,%1,%2,%3}, {%4,%5,%6,%7}, {%8,%9}, {%0,%1,%2,%3};"
        : "+f"(c[0]), "+f"(c[1]), "+f"(c[2]), "+f"(c[3])
        : "r"(a[0]), "r"(a[1]), "r"(a[2]), "r"(a[3]),
          "r"(bfr[0]), "r"(bfr[1]));
}

__device__ __forceinline__ uint32_t smem_u32(const void* p) {
    return (uint32_t)__cvta_generic_to_shared(p);
}

__device__ __forceinline__ void cp_async16(uint32_t dst, const void* src) {
    asm volatile("cp.async.cg.shared.global [%0], [%1], 16;" :: "r"(dst), "l"(src));
}

#define CP_COMMIT() asm volatile("cp.async.commit_group;")
#define CP_WAIT1()  asm volatile("cp.async.wait_group 1;")

// ---------------------------------------------------------------------------
// Kernel 0: round K/V to tf32 once, transpose (b,s,h,e) -> (b,h,s,e)
// ---------------------------------------------------------------------------
__global__ __launch_bounds__(256)
void preround_kv_kernel(const float* __restrict__ kk,
                        const float* __restrict__ vv_)
{
    const int i = (blockIdx.x * 256 + threadIdx.x) * 4;  // linear (b,s,h,e)
    const int e  = i & (EE - 1);
    const int t  = i >> 6;           // b*S*H + s*H + h
    const int h  = t & (HH - 1);
    const int t2 = t >> 3;           // b*S + s
    const int s  = t2 & (SSS - 1);
    const int b  = t2 >> 11;

    const float4 k4 = *(const float4*)&kk[i];
    const float4 v4 = *(const float4*)&vv_[i];
    const int o = (((b * HH + h) * SSS) + s) * EE + e;
    float4 ko, vo;
    ko.x = tf32r(k4.x); ko.y = tf32r(k4.y); ko.z = tf32r(k4.z); ko.w = tf32r(k4.w);
    vo.x = tf32r(v4.x); vo.y = tf32r(v4.y); vo.z = tf32r(v4.z); vo.w = tf32r(v4.w);
    *(float4*)&g_kt[o] = ko;
    *(float4*)&g_vt[o] = vo;
}

// ---------------------------------------------------------------------------
// Kernel 1: precompute the DAG + hard-mask additive term (fp16, log2 units)
// ---------------------------------------------------------------------------
__global__ __launch_bounds__(256)
void precompute_madd_kernel(const float* __restrict__ phi,
                            const float* __restrict__ uu_,
                            const int*   __restrict__ hard,
                            const float* __restrict__ log_tau,
                            const float* __restrict__ threshold,
                            const int*   __restrict__ causal_flag)
{
    const int row = blockIdx.y;          // h*LL + l
    const int l   = row & (LL - 1);
    const int s   = (blockIdx.x * 256 + threadIdx.x) * 4;
    if (causal_flag[0] && s > l) return;   // upper triangle never read (causal)

    float tau = __expf(log_tau[0]);
    tau = fminf(fmaxf(tau, 0.1f), 5.0f);
    const float inv_tau = 1.0f / tau;
    float thr = threshold[0];
    thr = fminf(fmaxf(thr, 0.01f), 0.99f);
    const float cmask = LOG2E * SCALE * MASK_SCALE;

    const int idx = row * SSS + s;
    const float4 ph = *(const float4*)&phi[idx];
    const float4 uv = *(const float4*)&uu_[idx];
    const int4   hm = *(const int4*)&hard[l * SSS + s];

    float o0, o1, o2, o3;
    {
        float g = __logf(__fdividef(uv.x + 1e-8f, 1.0f - uv.x + 1e-8f));
        float sg = __fdividef(1.0f, 1.0f + __expf(-(g + ph.x) * inv_tau));
        o0 = hm.x == 0 ? HARD_NEG : cmask * fminf(sg - thr, 0.0f);
    }
    {
        float g = __logf(__fdividef(uv.y + 1e-8f, 1.0f - uv.y + 1e-8f));
        float sg = __fdividef(1.0f, 1.0f + __expf(-(g + ph.y) * inv_tau));
        o1 = hm.y == 0 ? HARD_NEG : cmask * fminf(sg - thr, 0.0f);
    }
    {
        float g = __logf(__fdividef(uv.z + 1e-8f, 1.0f - uv.z + 1e-8f));
        float sg = __fdividef(1.0f, 1.0f + __expf(-(g + ph.z) * inv_tau));
        o2 = hm.z == 0 ? HARD_NEG : cmask * fminf(sg - thr, 0.0f);
    }
    {
        float g = __logf(__fdividef(uv.w + 1e-8f, 1.0f - uv.w + 1e-8f));
        float sg = __fdividef(1.0f, 1.0f + __expf(-(g + ph.w) * inv_tau));
        o3 = hm.w == 0 ? HARD_NEG : cmask * fminf(sg - thr, 0.0f);
    }
    __half2 h0 = __floats2half2_rn(o0, o1);
    __half2 h1 = __floats2half2_rn(o2, o3);
    uint2 pk;
    pk.x = *(uint32_t*)&h0;
    pk.y = *(uint32_t*)&h1;
    *(uint2*)&g_madd[idx] = pk;
}

// ---------------------------------------------------------------------------
// Kernel 2: flash attention on tensor cores (tf32 mma.sync m16n8k8).
// R12 pipeline (K, V AND madd double-buffered via cp.async, one commit group
// per tile, single wait point). madd is fp16 in smem; softmax in log2 units.
//
// Fragment layouts (lane = gid*4 + tig):
//   A (16x8 row):  a0=(gid,tig) a1=(gid+8,tig) a2=(gid,tig+4) a3=(gid+8,tig+4)
//   B (8x8 col):   b0=(k=tig,n=gid) b1=(k=tig+4,n=gid)
//   C (16x8):      c0=(gid,2tig) c1=(gid,2tig+1) c2=(gid+8,2tig) c3=(gid+8,2tig+1)
// ---------------------------------------------------------------------------
__global__ __launch_bounds__(NTHREADS)
void phi_softmax_mma_kernel(const float* __restrict__ q,
                            const int*   __restrict__ causal_flag,
                            float*       __restrict__ out)
{
    extern __shared__ float smem[];
    float*  Ks = smem;                            // [2][64][PADK]
    float*  Vs = Ks + 2 * BT * PADK;              // [2][64][PADV]
    float*  Ps = Vs + 2 * BT * PADV;              // [64][PADP]
    __half* Ms = (__half*)(Ps + BT * PADP);       // [2][64][PADM] halves

    const int b  = blockIdx.x;                    // batch fastest -> madd L2 reuse
    const int h  = blockIdx.y;
    const int lt = gridDim.z - 1 - blockIdx.z;    // heavy tiles first
    const int l0 = lt * BT;

    const int tid  = threadIdx.x;
    const int w    = tid >> 5;
    const int lane = tid & 31;
    const int gid  = lane >> 2;
    const int tig  = lane & 3;

    const int r0 = 16 * w + gid;                  // this thread's two rows
    const int r1 = r0 + 8;
    const int lg0 = l0 + r0;
    const int lg1 = l0 + r1;

    const int causal = causal_flag[0];
    const int nst = causal ? (lt + 1) : (SSS / BT);

    const float*  kt = g_kt + (b * HH + h) * (SSS * EE);
    const float*  vt = g_vt + (b * HH + h) * (SSS * EE);
    const __half* mt = g_madd + (h * LL + l0) * SSS;   // tile row base

    // per-thread cp.async slices
    const int cr  = tid >> 4;           // K/V base row (advance by 8)
    const int cec = (tid & 15) * 4;     // K/V e column
    const int mrw = tid >> 3;           // madd base row (advance by 16)
    const int mcc = (tid & 7) * 8;      // madd half-column (16B = 8 halves)

    // ---- prologue: issue tile 0 loads (one group: K0+V0+M0) ----
    #pragma unroll
    for (int c = 0; c < 8; c++) {
        const int r = cr + 8 * c;
        cp_async16(smem_u32(&Ks[r * PADK + cec]), &kt[r * EE + cec]);
        cp_async16(smem_u32(&Vs[r * PADV + cec]), &vt[r * EE + cec]);
    }
    #pragma unroll
    for (int j = 0; j < 4; j++) {
        const int r = mrw + 16 * j;
        cp_async16(smem_u32(&Ms[r * PADM + mcc]), &mt[r * SSS + mcc]);
    }
    CP_COMMIT();

    // ---- stage scaled Q into Ps, then load Q a-frags into registers ----
    for (int i = tid; i < BT * (EE / 4); i += NTHREADS) {
        int r  = i >> 4;
        int ec = (i & 15) * 4;
        float4 q4 = *(const float4*)&q[((b * LL + l0 + r) * HH + h) * EE + ec];
        Ps[r * PADP + ec + 0] = q4.x * SCALE_L;
        Ps[r * PADP + ec + 1] = q4.y * SCALE_L;
        Ps[r * PADP + ec + 2] = q4.z * SCALE_L;
        Ps[r * PADP + ec + 3] = q4.w * SCALE_L;
    }
    __syncthreads();

    uint32_t qa[8][4];                            // full K-dim of Q, tf32
    #pragma unroll
    for (int k8 = 0; k8 < 8; k8++) {
        qa[k8][0] = __float_as_uint(tf32r(Ps[r0 * PADP + 8 * k8 + tig]));
        qa[k8][1] = __float_as_uint(tf32r(Ps[r1 * PADP + 8 * k8 + tig]));
        qa[k8][2] = __float_as_uint(tf32r(Ps[r0 * PADP + 8 * k8 + tig + 4]));
        qa[k8][3] = __float_as_uint(tf32r(Ps[r1 * PADP + 8 * k8 + tig + 4]));
    }

    float o[8][4];
    float mrun0 = NEG_BIG, mrun1 = NEG_BIG, lrun0 = 0.0f, lrun1 = 0.0f;
    #pragma unroll
    for (int n = 0; n < 8; n++)
        #pragma unroll
        for (int j = 0; j < 4; j++) o[n][j] = 0.0f;

    for (int st = 0; st < nst; st++) {
        const int s0 = st * BT;
        const float*  Kb = Ks + (st & 1) * BT * PADK;
        const float*  Vb = Vs + (st & 1) * BT * PADV;
        const __half* Mb = Ms + (st & 1) * BT * PADM;

        // all warps done with previous iteration (GEMM2/softmax reads of the
        // buffers we are about to refill; Ps reads before softmax rewrites)
        __syncthreads();

        // ---- issue next tile's cp.async (empty group keeps wait uniform) ----
        if (st + 1 < nst) {
            float*  Kn = Ks + ((st + 1) & 1) * BT * PADK;
            float*  Vn = Vs + ((st + 1) & 1) * BT * PADV;
            __half* Mn = Ms + ((st + 1) & 1) * BT * PADM;
            const float*  ksrc = kt + (s0 + BT) * EE;
            const float*  vsrc = vt + (s0 + BT) * EE;
            const __half* msrc = mt + (s0 + BT);
            #pragma unroll
            for (int c = 0; c < 8; c++) {
                const int r = cr + 8 * c;
                cp_async16(smem_u32(&Kn[r * PADK + cec]), &ksrc[r * EE + cec]);
                cp_async16(smem_u32(&Vn[r * PADV + cec]), &vsrc[r * EE + cec]);
            }
            #pragma unroll
            for (int j = 0; j < 4; j++) {
                const int r = mrw + 16 * j;
                cp_async16(smem_u32(&Mn[r * PADM + mcc]), &msrc[r * SSS + mcc]);
            }
        }
        CP_COMMIT();
        CP_WAIT1();        // tile st resident; tile st+1 still in flight
        __syncthreads();

        // ---- GEMM1: scores (pre-scaled by SCALE*log2e via Q) ----
        float cc[8][4];
        #pragma unroll
        for (int n = 0; n < 8; n++)
            #pragma unroll
            for (int j = 0; j < 4; j++) cc[n][j] = 0.0f;

        #pragma unroll
        for (int n = 0; n < 8; n++) {
            const uint32_t* krow = (const uint32_t*)(Kb + (8 * n + gid) * PADK);
            #pragma unroll
            for (int k8 = 0; k8 < 8; k8++) {
                uint32_t bf[2];
                bf[0] = krow[8 * k8 + tig];
                bf[1] = krow[8 * k8 + tig + 4];
                mma_tf32(cc[n], qa[k8], bf);
            }
        }

        // ---- additive mask (fp16 smem) + causal + online softmax (base 2) ----
        const __half2* m0row = (const __half2*)(Mb + r0 * PADM);
        const __half2* m1row = (const __half2*)(Mb + r1 * PADM);
        float rmax0 = NEG_BIG, rmax1 = NEG_BIG;
        #pragma unroll
        for (int n = 0; n < 8; n++) {
            const int sc = s0 + 8 * n + 2 * tig;
            const float2 a0 = __half22float2(m0row[4 * n + tig]);
            const float2 a1 = __half22float2(m1row[4 * n + tig]);
            float x0 = cc[n][0] + a0.x;
            float x1 = cc[n][1] + a0.y;
            float x2 = cc[n][2] + a1.x;
            float x3 = cc[n][3] + a1.y;
            if (causal) {
                if (sc     > lg0) x0 = NEG_BIG;
                if (sc + 1 > lg0) x1 = NEG_BIG;
                if (sc     > lg1) x2 = NEG_BIG;
                if (sc + 1 > lg1) x3 = NEG_BIG;
            }
            cc[n][0] = x0; cc[n][1] = x1; cc[n][2] = x2; cc[n][3] = x3;
            rmax0 = fmaxf(rmax0, fmaxf(x0, x1));
            rmax1 = fmaxf(rmax1, fmaxf(x2, x3));
        }
        rmax0 = fmaxf(rmax0, __shfl_xor_sync(0xffffffffu, rmax0, 1, 4));
        rmax0 = fmaxf(rmax0, __shfl_xor_sync(0xffffffffu, rmax0, 2, 4));
        rmax1 = fmaxf(rmax1, __shfl_xor_sync(0xffffffffu, rmax1, 1, 4));
        rmax1 = fmaxf(rmax1, __shfl_xor_sync(0xffffffffu, rmax1, 2, 4));

        const float mnew0 = fmaxf(mrun0, rmax0);
        const float mnew1 = fmaxf(mrun1, rmax1);
        const float al0 = exp2f(mrun0 - mnew0);
        const float al1 = exp2f(mrun1 - mnew1);
        mrun0 = mnew0; mrun1 = mnew1;

        float ls0 = 0.0f, ls1 = 0.0f;
        #pragma unroll
        for (int n = 0; n < 8; n++) {
            // Fully-masked-so-far rows give p=1 garbage; annihilated once the
            // first real entry (open diagonal, madd >= ~-1790 >> -60000)
            // makes alpha=exp2(-huge)=0.
            float p0 = exp2f(cc[n][0] - mnew0);
            float p1 = exp2f(cc[n][1] - mnew0);
            float p2 = exp2f(cc[n][2] - mnew1);
            float p3 = exp2f(cc[n][3] - mnew1);
            ls0 += p0 + p1;
            ls1 += p2 + p3;
            const int pc = 8 * n + 2 * tig;
            *(float2*)&Ps[r0 * PADP + pc] = make_float2(tf32r(p0), tf32r(p1));
            *(float2*)&Ps[r1 * PADP + pc] = make_float2(tf32r(p2), tf32r(p3));
        }
        lrun0 = lrun0 * al0 + ls0;
        lrun1 = lrun1 * al1 + ls1;
        #pragma unroll
        for (int n = 0; n < 8; n++) {
            o[n][0] *= al0; o[n][1] *= al0;
            o[n][2] *= al1; o[n][3] *= al1;
        }
        __syncwarp();   // P rows are warp-private; order STS before LDS

        // ---- GEMM2: out += P @ V (V already tf32) ----
        #pragma unroll
        for (int k8 = 0; k8 < 8; k8++) {
            uint32_t pa[4];
            const uint32_t* Pu = (const uint32_t*)Ps;
            pa[0] = Pu[r0 * PADP + 8 * k8 + tig];
            pa[1] = Pu[r1 * PADP + 8 * k8 + tig];
            pa[2] = Pu[r0 * PADP + 8 * k8 + tig + 4];
            pa[3] = Pu[r1 * PADP + 8 * k8 + tig + 4];
            const uint32_t* v0 = (const uint32_t*)(Vb + (8 * k8 + tig) * PADV);
            const uint32_t* v1 = (const uint32_t*)(Vb + (8 * k8 + tig + 4) * PADV);
            #pragma unroll
            for (int n = 0; n < 8; n++) {
                uint32_t vb[2];
                vb[0] = v0[8 * n + gid];
                vb[1] = v1[8 * n + gid];
                mma_tf32(o[n], pa, vb);
            }
        }
    }

    // ---- finalize: reduce row sums across quad, normalize, store ----
    lrun0 += __shfl_xor_sync(0xffffffffu, lrun0, 1, 4);
    lrun0 += __shfl_xor_sync(0xffffffffu, lrun0, 2, 4);
    lrun1 += __shfl_xor_sync(0xffffffffu, lrun1, 1, 4);
    lrun1 += __shfl_xor_sync(0xffffffffu, lrun1, 2, 4);
    const float inv0 = 1.0f / lrun0;   // diagonal always open -> lrun > 0
    const float inv1 = 1.0f / lrun1;

    float* out0 = out + ((b * LL + lg0) * HH + h) * EE;
    float* out1 = out + ((b * LL + lg1) * HH + h) * EE;
    #pragma unroll
    for (int n = 0; n < 8; n++) {
        const int ec = 8 * n + 2 * tig;
        *(float2*)&out0[ec] = make_float2(o[n][0] * inv0, o[n][1] * inv0);
        *(float2*)&out1[ec] = make_float2(o[n][2] * inv1, o[n][3] * inv1);
    }
}

extern "C" void kernel_launch(void* const* d_in, const int* in_sizes, int n_in,
                              void* d_out, int out_size)
{
    const float* q        = (const float*)d_in[0];
    const float* k        = (const float*)d_in[1];
    const float* v        = (const float*)d_in[2];
    const int*   causal   = (const int*)d_in[6];
    const int*   hard     = (const int*)d_in[7];
    const float* phi      = (const float*)d_in[8];
    const float* log_tau  = (const float*)d_in[9];
    const float* thr      = (const float*)d_in[10];
    const float* u        = (const float*)d_in[11];
    float* out            = (float*)d_out;

    // Kernel 0: pre-round K/V to tf32, transpose to [b][h][s][e]
    {
        const int n4 = BB * SSS * HH * EE / 4;
        preround_kv_kernel<<<n4 / 256, 256>>>(k, v);
    }

    // Kernel 1: precompute additive mask (batch-independent, fp16, log2 units)
    {
        dim3 grid(SSS / (256 * 4), HH * LL);
        precompute_madd_kernel<<<grid, 256>>>(phi, u, hard, log_tau, thr, causal);
    }

    // Kernel 2: pipelined tensor-core attention (madd via cp.async)
    {
        const int smem_bytes =
            (2 * BT * PADK + 2 * BT * PADV + BT * PADP) * sizeof(float)
            + 2 * BT * PADM * sizeof(__half);
        cudaFuncSetAttribute(phi_softmax_mma_kernel,
                             cudaFuncAttributeMaxDynamicSharedMemorySize, smem_bytes);
        dim3 grid(BB, HH, LL / BT);
        phi_softmax_mma_kernel<<<grid, NTHREADS, smem_bytes>>>(q, causal, out);
    }
}

// round 17
// speedup vs baseline: 1.6737x; 1.2072x over previous
#include <cuda_runtime.h>
#include <cuda_bf16.h>
#include <cuda_fp16.h>
#include <cstdint>

// Problem constants (fixed by setup_inputs)
#define BB 2
#define LL 2048
#define SSS 2048
#define HH 8
#define EE 64

#define BT 64        // L and S tile
#define NTHREADS 128 // 4 warps; warp w owns rows 16w..16w+15

// smem strides in HALVES (all give conflict-free bank pattern 4*gid+tig)
#define PADKH 72     // K rows (s-major, e contiguous): 144B rows
#define PADVPH 136   // V spair rows ([spair][e][2]): 272B rows
#define PADPH 72     // P rows (l-major, s contiguous); also Q staging
#define PADM  72     // madd rows (l-major, s contiguous fp16)

#define MASK_SCALE 10000.0f
#define NEG_BIG  (-1e30f)
#define HARD_NEG (-60000.0f)   // fp16-representable sentinel for hard mask
#define LOG2E 1.44269504f
#define SCALE 0.125f            // 1/sqrt(64)
#define SCALE_L (SCALE * LOG2E) // folded into Q; softmax uses exp2

// Precomputed additive mask in LOG2 UNITS, fp16:
//   madd[h,l,s] = hard==0 ? HARD_NEG : LOG2E * SCALE * 10000 * min(sig-thr, 0)
__device__ __half g_madd[HH * LL * SSS];
// K: fp16, [b][h][s][e]
__device__ __half g_kt[BB * HH * SSS * EE];
// V: fp16, s-paired: [b][h][spair][e][2]  (half2 of adjacent s rows per e)
__device__ __half g_vt[BB * HH * SSS * EE];

// ---------------------------------------------------------------------------
// helpers
// ---------------------------------------------------------------------------
__device__ __forceinline__ void mma_f16(float c[4], const uint32_t a[4],
                                        uint32_t b0, uint32_t b1) {
    asm volatile(
        "mma.sync.aligned.m16n8k16.row.col.f32.f16.f16.f32 "
        "{%0,%1,%2,%3}, {%4,%5,%6,%7}, {%8,%9}, {%0,%1,%2,%3};"
        : "+f"(c[0]), "+f"(c[1]), "+f"(c[2]), "+f"(c[3])
        : "r"(a[0]), "r"(a[1]), "r"(a[2]), "r"(a[3]),
          "r"(b0), "r"(b1));
}

__device__ __forceinline__ uint32_t smem_u32(const void* p) {
    return (uint32_t)__cvta_generic_to_shared(p);
}

__device__ __forceinline__ void cp_async16(uint32_t dst, const void* src) {
    asm volatile("cp.async.cg.shared.global [%0], [%1], 16;" :: "r"(dst), "l"(src));
}

#define CP_COMMIT() asm volatile("cp.async.commit_group;")
#define CP_WAIT1()  asm volatile("cp.async.wait_group 1;")

__device__ __forceinline__ uint32_t h2u(__half2 h) {
    return *(uint32_t*)&h;
}

// ---------------------------------------------------------------------------
// Kernel 0: convert K/V to fp16. K -> [b][h][s][e]; V -> [b][h][spair][e][2].
// One thread handles (b, spair, h, e0..e0+3) for BOTH s rows of the pair,
// so all stores are fully coalesced (8B for K, 16B for V).
// ---------------------------------------------------------------------------
__global__ __launch_bounds__(256)
void preround_kv_kernel(const float* __restrict__ kk,
                        const float* __restrict__ vv_)
{
    const int idx = blockIdx.x * 256 + threadIdx.x;  // (b, sp, h, e4)
    const int e4 = idx & 15;
    const int h  = (idx >> 4) & 7;
    const int sp = (idx >> 7) & 1023;
    const int b  = idx >> 17;
    const int e0 = e4 * 4;
    const int s  = sp * 2;

    const int src0 = ((b * SSS + s)     * HH + h) * EE + e0;
    const int src1 = ((b * SSS + s + 1) * HH + h) * EE + e0;
    const float4 k0 = *(const float4*)&kk[src0];
    const float4 k1 = *(const float4*)&kk[src1];
    const float4 v0 = *(const float4*)&vv_[src0];
    const float4 v1 = *(const float4*)&vv_[src1];

    // K: two rows of 4 contiguous halves (8B stores)
    {
        __half* kd0 = g_kt + ((b * HH + h) * SSS + s) * EE + e0;
        uint2 p0, p1;
        p0.x = h2u(__floats2half2_rn(k0.x, k0.y));
        p0.y = h2u(__floats2half2_rn(k0.z, k0.w));
        p1.x = h2u(__floats2half2_rn(k1.x, k1.y));
        p1.y = h2u(__floats2half2_rn(k1.z, k1.w));
        *(uint2*)kd0        = p0;
        *(uint2*)(kd0 + EE) = p1;
    }
    // V: s-paired half2 per e -> 8 contiguous halves (16B store)
    {
        __half* vd = g_vt + (b * HH + h) * (SSS * EE) + sp * 128 + e0 * 2;
        uint4 vp;
        vp.x = h2u(__floats2half2_rn(v0.x, v1.x));
        vp.y = h2u(__floats2half2_rn(v0.y, v1.y));
        vp.z = h2u(__floats2half2_rn(v0.z, v1.z));
        vp.w = h2u(__floats2half2_rn(v0.w, v1.w));
        *(uint4*)vd = vp;
    }
}

// ---------------------------------------------------------------------------
// Kernel 1: precompute the DAG + hard-mask additive term (fp16, log2 units)
// ---------------------------------------------------------------------------
__global__ __launch_bounds__(256)
void precompute_madd_kernel(const float* __restrict__ phi,
                            const float* __restrict__ uu_,
                            const int*   __restrict__ hard,
                            const float* __restrict__ log_tau,
                            const float* __restrict__ threshold,
                            const int*   __restrict__ causal_flag)
{
    const int row = blockIdx.y;          // h*LL + l
    const int l   = row & (LL - 1);
    const int s   = (blockIdx.x * 256 + threadIdx.x) * 4;
    if (causal_flag[0] && s > l) return;   // upper triangle never read (causal)

    float tau = __expf(log_tau[0]);
    tau = fminf(fmaxf(tau, 0.1f), 5.0f);
    const float inv_tau = 1.0f / tau;
    float thr = threshold[0];
    thr = fminf(fmaxf(thr, 0.01f), 0.99f);
    const float cmask = LOG2E * SCALE * MASK_SCALE;

    const int idx = row * SSS + s;
    const float4 ph = *(const float4*)&phi[idx];
    const float4 uv = *(const float4*)&uu_[idx];
    const int4   hm = *(const int4*)&hard[l * SSS + s];

    float o0, o1, o2, o3;
    {
        float g = __logf(__fdividef(uv.x + 1e-8f, 1.0f - uv.x + 1e-8f));
        float sg = __fdividef(1.0f, 1.0f + __expf(-(g + ph.x) * inv_tau));
        o0 = hm.x == 0 ? HARD_NEG : cmask * fminf(sg - thr, 0.0f);
    }
    {
        float g = __logf(__fdividef(uv.y + 1e-8f, 1.0f - uv.y + 1e-8f));
        float sg = __fdividef(1.0f, 1.0f + __expf(-(g + ph.y) * inv_tau));
        o1 = hm.y == 0 ? HARD_NEG : cmask * fminf(sg - thr, 0.0f);
    }
    {
        float g = __logf(__fdividef(uv.z + 1e-8f, 1.0f - uv.z + 1e-8f));
        float sg = __fdividef(1.0f, 1.0f + __expf(-(g + ph.z) * inv_tau));
        o2 = hm.z == 0 ? HARD_NEG : cmask * fminf(sg - thr, 0.0f);
    }
    {
        float g = __logf(__fdividef(uv.w + 1e-8f, 1.0f - uv.w + 1e-8f));
        float sg = __fdividef(1.0f, 1.0f + __expf(-(g + ph.w) * inv_tau));
        o3 = hm.w == 0 ? HARD_NEG : cmask * fminf(sg - thr, 0.0f);
    }
    uint2 pk;
    pk.x = h2u(__floats2half2_rn(o0, o1));
    pk.y = h2u(__floats2half2_rn(o2, o3));
    *(uint2*)&g_madd[idx] = pk;
}

// ---------------------------------------------------------------------------
// Kernel 2: flash attention, fp16 mma.sync m16n8k16, fp32 accumulate.
// Pipeline/sync structure IDENTICAL to the R16 winner (K,V,madd double-
// buffered via cp.async, one commit group per tile, single wait point).
//
// Fragment layouts (lane = gid*4 + tig):
//   A (16x16 row):  a0={A[gid][2tig..+1]}  a1={A[gid+8][2tig..+1]}
//                   a2={A[gid][2tig+8..+9]} a3={A[gid+8][2tig+8..+9]}
//   B (16x8 col):   b0={B[2tig][gid],B[2tig+1][gid]}  b1={B[2tig+8..][gid]}
//   C (16x8 f32):   c0=(gid,2tig) c1=(gid,2tig+1) c2/c3=(gid+8,...)
// ---------------------------------------------------------------------------
__global__ __launch_bounds__(NTHREADS, 3)
void phi_softmax_mma_kernel(const float* __restrict__ q,
                            const int*   __restrict__ causal_flag,
                            float*       __restrict__ out)
{
    extern __shared__ __align__(16) char smem_raw[];
    __half* Ksh = (__half*)smem_raw;               // [2][64][PADKH]
    __half* Vsh = Ksh + 2 * BT * PADKH;            // [2][32][PADVPH]
    __half* Psh = Vsh + 2 * 32 * PADVPH;           // [64][PADPH]; Q staging too
    __half* Msh = Psh + BT * PADPH;                // [2][64][PADM]

    const int b  = blockIdx.x;                    // batch fastest -> madd L2 reuse
    const int h  = blockIdx.y;
    const int lt = gridDim.z - 1 - blockIdx.z;    // heavy tiles first
    const int l0 = lt * BT;

    const int tid  = threadIdx.x;
    const int w    = tid >> 5;
    const int lane = tid & 31;
    const int gid  = lane >> 2;
    const int tig  = lane & 3;

    const int r0 = 16 * w + gid;                  // this thread's two rows
    const int r1 = r0 + 8;
    const int lg0 = l0 + r0;
    const int lg1 = l0 + r1;

    const int causal = causal_flag[0];
    const int nst = causal ? (lt + 1) : (SSS / BT);

    const __half* kt = g_kt + (b * HH + h) * (SSS * EE);   // + s*64
    const __half* vt = g_vt + (b * HH + h) * (SSS * EE);   // + s*64 (=spair*128)
    const __half* mt = g_madd + (h * LL + l0) * SSS;       // tile row base

    // per-thread cp.async slices (16B chunks)
    const int krw = tid >> 3;           // K/M rows 0..15 (+16j)
    const int kcc = (tid & 7) * 8;      // half column
    const int vrw = tid >> 4;           // V spair rows 0..7 (+8j)
    const int vcc = (tid & 15) * 8;     // half column

    // ---- prologue: issue tile 0 loads (one group: K0+V0+M0) ----
    #pragma unroll
    for (int j = 0; j < 4; j++) {
        const int r = krw + 16 * j;
        cp_async16(smem_u32(&Ksh[r * PADKH + kcc]), &kt[r * EE + kcc]);
        cp_async16(smem_u32(&Msh[r * PADM + kcc]),  &mt[r * SSS + kcc]);
        const int vr = vrw + 8 * j;
        cp_async16(smem_u32(&Vsh[vr * PADVPH + vcc]), &vt[vr * 128 + vcc]);
    }
    CP_COMMIT();

    // ---- stage scaled Q (fp16) into Psh, then load Q a-frags ----
    for (int i = tid; i < BT * (EE / 4); i += NTHREADS) {
        int r  = i >> 4;
        int ec = (i & 15) * 4;
        float4 q4 = *(const float4*)&q[((b * LL + l0 + r) * HH + h) * EE + ec];
        uint2 qp;
        qp.x = h2u(__floats2half2_rn(q4.x * SCALE_L, q4.y * SCALE_L));
        qp.y = h2u(__floats2half2_rn(q4.z * SCALE_L, q4.w * SCALE_L));
        *(uint2*)&Psh[r * PADPH + ec] = qp;
    }
    __syncthreads();

    uint32_t qa[4][4];                            // Q a-frags, 4 k16 blocks
    #pragma unroll
    for (int kb = 0; kb < 4; kb++) {
        qa[kb][0] = *(uint32_t*)&Psh[r0 * PADPH + 16 * kb + 2 * tig];
        qa[kb][1] = *(uint32_t*)&Psh[r1 * PADPH + 16 * kb + 2 * tig];
        qa[kb][2] = *(uint32_t*)&Psh[r0 * PADPH + 16 * kb + 2 * tig + 8];
        qa[kb][3] = *(uint32_t*)&Psh[r1 * PADPH + 16 * kb + 2 * tig + 8];
    }
    // Q-frag reads are ordered before st=0's P writes by the loop barriers.

    float o[8][4];
    float mrun0 = NEG_BIG, mrun1 = NEG_BIG, lrun0 = 0.0f, lrun1 = 0.0f;
    #pragma unroll
    for (int n = 0; n < 8; n++)
        #pragma unroll
        for (int j = 0; j < 4; j++) o[n][j] = 0.0f;

    for (int st = 0; st < nst; st++) {
        const int s0 = st * BT;
        const __half* Kb = Ksh + (st & 1) * BT * PADKH;
        const __half* Vb = Vsh + (st & 1) * 32 * PADVPH;
        const __half* Mb = Msh + (st & 1) * BT * PADM;

        // all warps done with previous iteration (GEMM2/softmax reads of the
        // buffers we are about to refill; P/Q reads before softmax rewrites)
        __syncthreads();

        // ---- issue next tile's cp.async (empty group keeps wait uniform) ----
        if (st + 1 < nst) {
            __half* Kn = Ksh + ((st + 1) & 1) * BT * PADKH;
            __half* Vn = Vsh + ((st + 1) & 1) * 32 * PADVPH;
            __half* Mn = Msh + ((st + 1) & 1) * BT * PADM;
            const __half* ksrc = kt + (s0 + BT) * EE;
            const __half* vsrc = vt + (s0 + BT) * EE;
            const __half* msrc = mt + (s0 + BT);
            #pragma unroll
            for (int j = 0; j < 4; j++) {
                const int r = krw + 16 * j;
                cp_async16(smem_u32(&Kn[r * PADKH + kcc]), &ksrc[r * EE + kcc]);
                cp_async16(smem_u32(&Mn[r * PADM + kcc]),  &msrc[r * SSS + kcc]);
                const int vr = vrw + 8 * j;
                cp_async16(smem_u32(&Vn[vr * PADVPH + vcc]), &vsrc[vr * 128 + vcc]);
            }
        }
        CP_COMMIT();
        CP_WAIT1();        // tile st resident; tile st+1 still in flight
        __syncthreads();

        // ---- GEMM1: scores (pre-scaled by SCALE*log2e via Q) ----
        float cc[8][4];
        #pragma unroll
        for (int n = 0; n < 8; n++)
            #pragma unroll
            for (int j = 0; j < 4; j++) cc[n][j] = 0.0f;

        #pragma unroll
        for (int n = 0; n < 8; n++) {
            const __half* krow = Kb + (8 * n + gid) * PADKH;
            #pragma unroll
            for (int kb = 0; kb < 4; kb++) {
                uint32_t b0 = *(uint32_t*)(krow + 16 * kb + 2 * tig);
                uint32_t b1 = *(uint32_t*)(krow + 16 * kb + 2 * tig + 8);
                mma_f16(cc[n], qa[kb], b0, b1);
            }
        }

        // ---- additive mask (fp16 smem) + causal + online softmax (base 2) ----
        const __half2* m0row = (const __half2*)(Mb + r0 * PADM);
        const __half2* m1row = (const __half2*)(Mb + r1 * PADM);
        float rmax0 = NEG_BIG, rmax1 = NEG_BIG;
        #pragma unroll
        for (int n = 0; n < 8; n++) {
            const int sc = s0 + 8 * n + 2 * tig;
            const float2 a0 = __half22float2(m0row[4 * n + tig]);
            const float2 a1 = __half22float2(m1row[4 * n + tig]);
            float x0 = cc[n][0] + a0.x;
            float x1 = cc[n][1] + a0.y;
            float x2 = cc[n][2] + a1.x;
            float x3 = cc[n][3] + a1.y;
            if (causal) {
                if (sc     > lg0) x0 = NEG_BIG;
                if (sc + 1 > lg0) x1 = NEG_BIG;
                if (sc     > lg1) x2 = NEG_BIG;
                if (sc + 1 > lg1) x3 = NEG_BIG;
            }
            cc[n][0] = x0; cc[n][1] = x1; cc[n][2] = x2; cc[n][3] = x3;
            rmax0 = fmaxf(rmax0, fmaxf(x0, x1));
            rmax1 = fmaxf(rmax1, fmaxf(x2, x3));
        }
        rmax0 = fmaxf(rmax0, __shfl_xor_sync(0xffffffffu, rmax0, 1, 4));
        rmax0 = fmaxf(rmax0, __shfl_xor_sync(0xffffffffu, rmax0, 2, 4));
        rmax1 = fmaxf(rmax1, __shfl_xor_sync(0xffffffffu, rmax1, 1, 4));
        rmax1 = fmaxf(rmax1, __shfl_xor_sync(0xffffffffu, rmax1, 2, 4));

        const float mnew0 = fmaxf(mrun0, rmax0);
        const float mnew1 = fmaxf(mrun1, rmax1);
        const float al0 = exp2f(mrun0 - mnew0);
        const float al1 = exp2f(mrun1 - mnew1);
        mrun0 = mnew0; mrun1 = mnew1;

        float ls0 = 0.0f, ls1 = 0.0f;
        #pragma unroll
        for (int n = 0; n < 8; n++) {
            // Fully-masked-so-far rows give p=1 garbage; annihilated once the
            // first real entry (open diagonal, madd >= ~-1790 >> -60000)
            // makes alpha=exp2(-huge)=0.
            float p0 = exp2f(cc[n][0] - mnew0);
            float p1 = exp2f(cc[n][1] - mnew0);
            float p2 = exp2f(cc[n][2] - mnew1);
            float p3 = exp2f(cc[n][3] - mnew1);
            ls0 += p0 + p1;
            ls1 += p2 + p3;
            *(__half2*)&Psh[r0 * PADPH + 8 * n + 2 * tig] = __floats2half2_rn(p0, p1);
            *(__half2*)&Psh[r1 * PADPH + 8 * n + 2 * tig] = __floats2half2_rn(p2, p3);
        }
        lrun0 = lrun0 * al0 + ls0;
        lrun1 = lrun1 * al1 + ls1;
        #pragma unroll
        for (int n = 0; n < 8; n++) {
            o[n][0] *= al0; o[n][1] *= al0;
            o[n][2] *= al1; o[n][3] *= al1;
        }
        __syncwarp();   // P rows are warp-private; order STS before LDS

        // ---- GEMM2: out += P @ V ----
        #pragma unroll
        for (int kb = 0; kb < 4; kb++) {
            uint32_t pa[4];
            pa[0] = *(uint32_t*)&Psh[r0 * PADPH + 16 * kb + 2 * tig];
            pa[1] = *(uint32_t*)&Psh[r1 * PADPH + 16 * kb + 2 * tig];
            pa[2] = *(uint32_t*)&Psh[r0 * PADPH + 16 * kb + 2 * tig + 8];
            pa[3] = *(uint32_t*)&Psh[r1 * PADPH + 16 * kb + 2 * tig + 8];
            const __half* v0 = Vb + (8 * kb + tig) * PADVPH;
            const __half* v1 = Vb + (8 * kb + tig + 4) * PADVPH;
            #pragma unroll
            for (int n = 0; n < 8; n++) {
                uint32_t b0 = *(uint32_t*)(v0 + (8 * n + gid) * 2);
                uint32_t b1 = *(uint32_t*)(v1 + (8 * n + gid) * 2);
                mma_f16(o[n], pa, b0, b1);
            }
        }
    }

    // ---- finalize: reduce row sums across quad, normalize, store ----
    lrun0 += __shfl_xor_sync(0xffffffffu, lrun0, 1, 4);
    lrun0 += __shfl_xor_sync(0xffffffffu, lrun0, 2, 4);
    lrun1 += __shfl_xor_sync(0xffffffffu, lrun1, 1, 4);
    lrun1 += __shfl_xor_sync(0xffffffffu, lrun1, 2, 4);
    const float inv0 = 1.0f / lrun0;   // diagonal always open -> lrun > 0
    const float inv1 = 1.0f / lrun1;

    float* out0 = out + ((b * LL + lg0) * HH + h) * EE;
    float* out1 = out + ((b * LL + lg1) * HH + h) * EE;
    #pragma unroll
    for (int n = 0; n < 8; n++) {
        const int ec = 8 * n + 2 * tig;
        *(float2*)&out0[ec] = make_float2(o[n][0] * inv0, o[n][1] * inv0);
        *(float2*)&out1[ec] = make_float2(o[n][2] * inv1, o[n][3] * inv1);
    }
}

extern "C" void kernel_launch(void* const* d_in, const int* in_sizes, int n_in,
                              void* d_out, int out_size)
{
    const float* q        = (const float*)d_in[0];
    const float* k        = (const float*)d_in[1];
    const float* v        = (const float*)d_in[2];
    const int*   causal   = (const int*)d_in[6];
    const int*   hard     = (const int*)d_in[7];
    const float* phi      = (const float*)d_in[8];
    const float* log_tau  = (const float*)d_in[9];
    const float* thr      = (const float*)d_in[10];
    const float* u        = (const float*)d_in[11];
    float* out            = (float*)d_out;

    // Kernel 0: convert K/V to fp16 (K row-major, V s-paired)
    {
        const int nthr = BB * (SSS / 2) * HH * (EE / 4);  // 262144
        preround_kv_kernel<<<nthr / 256, 256>>>(k, v);
    }

    // Kernel 1: precompute additive mask (batch-independent, fp16, log2 units)
    {
        dim3 grid(SSS / (256 * 4), HH * LL);
        precompute_madd_kernel<<<grid, 256>>>(phi, u, hard, log_tau, thr, causal);
    }

    // Kernel 2: pipelined fp16 tensor-core attention
    {
        const int smem_bytes =
            (2 * BT * PADKH + 2 * 32 * PADVPH + BT * PADPH + 2 * BT * PADM)
            * (int)sizeof(__half);
        cudaFuncSetAttribute(phi_softmax_mma_kernel,
                             cudaFuncAttributeMaxDynamicSharedMemorySize, smem_bytes);
        dim3 grid(BB, HH, LL / BT);
        phi_softmax_mma_kernel<<<grid, NTHREADS, smem_bytes>>>(q, causal, out);
    }
}